// round 1
// baseline (speedup 1.0000x reference)
#include <cuda_runtime.h>
#include <math.h>

#define HH   8
#define SS   1024
#define DDIM 64
#define KG   10
#define NLUT 4096
#define BM   64
#define BN   64

#define D_LO (-0.05f)
#define D_HI (10.05f)
#define E_LO (-0.05f)
#define E_HI (5.05f)

// Scratch (no runtime allocation allowed): transposed Q/K and the bias LUTs.
__device__ float  g_Qt[HH * DDIM * SS];   // [h][d][s]
__device__ float  g_Kt[HH * DDIM * SS];   // [h][d][s]
__device__ float2 g_lutD[NLUT];           // {value, delta-to-next}
__device__ float2 g_lutE[NLUT];

// ---------------------------------------------------------------------------
// Exact bias function (RBF features -> Linear -> exact GELU -> Linear).
// Evaluated only NLUT*2*2 times total, so full-precision expf/erff.
// ---------------------------------------------------------------------------
__device__ __forceinline__ float bias_eval(
    float x,
    const float* __restrict__ mu, const float* __restrict__ sg,
    const float* __restrict__ bb,
    const float* __restrict__ W1, const float* __restrict__ b1,
    const float* __restrict__ W2, const float* __restrict__ b2)
{
    float psi[KG];
#pragma unroll
    for (int k = 0; k < KG; k++) {
        float s = sg[k];
        float z = (x + bb[k] - mu[k]) / s;
        psi[k] = expf(-0.5f * z * z) * (0.3989422804014327f / s);
    }
    float o = b2[0];
#pragma unroll
    for (int l = 0; l < KG; l++) {
        float a = b1[l];
#pragma unroll
        for (int k = 0; k < KG; k++) a = fmaf(psi[k], W1[l * KG + k], a);
        float g = 0.5f * a * (1.0f + erff(a * 0.7071067811865476f));
        o = fmaf(g, W2[l], o);
    }
    return o;
}

__global__ void build_lut_kernel(
    const float* __restrict__ muD, const float* __restrict__ sgD, const float* __restrict__ bD,
    const float* __restrict__ muE, const float* __restrict__ sgE, const float* __restrict__ bE,
    const float* __restrict__ W1,  const float* __restrict__ b1,
    const float* __restrict__ W2,  const float* __restrict__ b2)
{
    int i = blockIdx.x * blockDim.x + threadIdx.x;
    if (i >= 2 * NLUT) return;
    int which = i >> 12;        // 0 = distance table, 1 = energy table
    int e     = i & (NLUT - 1);

    float lo = which ? E_LO : D_LO;
    float hi = which ? E_HI : D_HI;
    float dx = (hi - lo) / (float)(NLUT - 1);
    float x0 = lo + (float)e * dx;

    const float* mu = which ? muE : muD;
    const float* sg = which ? sgE : sgD;
    const float* bb = which ? bE  : bD;

    float f0 = bias_eval(x0,      mu, sg, bb, W1, b1, W2, b2);
    float f1 = bias_eval(x0 + dx, mu, sg, bb, W1, b1, W2, b2);
    float2 entry = make_float2(f0, f1 - f0);
    if (which) g_lutE[e] = entry; else g_lutD[e] = entry;
}

// ---------------------------------------------------------------------------
// Pre-transpose Q and K: [h][s][d] -> [h][d][s] so the attention kernel can do
// conflict-free d-major smem tiles with LDS.128.
// ---------------------------------------------------------------------------
__global__ void transpose_qk_kernel(const float* __restrict__ Q,
                                    const float* __restrict__ K)
{
    __shared__ float tile[32][33];
    int h = blockIdx.z >> 1;
    const float* src = (blockIdx.z & 1) ? K : Q;
    float*       dst = (blockIdx.z & 1) ? g_Kt : g_Qt;
    int s0 = blockIdx.x * 32;
    int d0 = blockIdx.y * 32;
    int tx = threadIdx.x, ty = threadIdx.y;
#pragma unroll
    for (int k = 0; k < 32; k += 8)
        tile[ty + k][tx] = src[((h * SS) + (s0 + ty + k)) * DDIM + d0 + tx];
    __syncthreads();
#pragma unroll
    for (int k = 0; k < 32; k += 8)
        dst[((h * DDIM) + (d0 + ty + k)) * SS + s0 + tx] = tile[tx][ty + k];
}

// ---------------------------------------------------------------------------
// Fused flash-attention with LUT biases.
// Grid: (S/BM, H). Block: 256 threads = 16x16; thread (ty,tx) owns a 4x4
// micro-tile: rows 4ty..4ty+3, cols/dims 4tx..4tx+3.
// Dynamic smem (128KB): Qt[64][64] | Kt[64][64] | V[64][64] | Pswz[64][64]
//                       | lutD float2[4096] | lutE float2[4096]
// ---------------------------------------------------------------------------
__global__ __launch_bounds__(256, 1) void attn_kernel(
    const float* __restrict__ V,
    const float* __restrict__ dist,
    const float* __restrict__ energy,
    const int*   __restrict__ mask,
    float*       __restrict__ out)
{
    extern __shared__ float sm[];
    float*  sQt = sm;                 // [d][row]   4096 floats
    float*  sKt = sm + 4096;          // [d][col]   4096 floats
    float*  sVs = sm + 8192;          // [j][dim]   4096 floats
    float*  sP  = sm + 12288;         // [j][row]   4096 floats, XOR-swizzled
    float2* sLD = (float2*)(sm + 16384);
    float2* sLE = (float2*)(sm + 24576);

    const int tid = threadIdx.x;
    const int tx  = tid & 15;
    const int ty  = tid >> 4;
    const int h   = blockIdx.y;
    const int i0  = blockIdx.x * BM;

    const float SCALE = 0.08838834764831845f;   // 1/sqrt(2*D)
    const float DINV  = (float)(NLUT - 1) / (D_HI - D_LO);
    const float EINV  = (float)(NLUT - 1) / (E_HI - E_LO);

    // LUTs -> shared (once per block)
    for (int i = tid; i < NLUT; i += 256) { sLD[i] = g_lutD[i]; sLE[i] = g_lutE[i]; }

    // Q tile (d-major), coalesced float4 copy
#pragma unroll
    for (int it = 0; it < 4; it++) {
        int idx = tid * 4 + it * 1024;
        int d = idx >> 6, r = idx & 63;
        *(float4*)&sQt[idx] = *(const float4*)&g_Qt[(h * DDIM + d) * SS + i0 + r];
    }

    float acc[4][4] = {};
    float mrow[4]   = {-1e30f, -1e30f, -1e30f, -1e30f};
    float lrow[4]   = {};

    for (int jt = 0; jt < SS / BN; jt++) {
        const int j0 = jt * BN;
        __syncthreads();   // previous iteration done reading sKt/sVs/sP

        // K tile (d-major) + V tile (natural), coalesced float4 copies
#pragma unroll
        for (int it = 0; it < 4; it++) {
            int idx = tid * 4 + it * 1024;
            int d = idx >> 6, r = idx & 63;
            *(float4*)&sKt[idx] = *(const float4*)&g_Kt[(h * DDIM + d) * SS + j0 + r];
            *(float4*)&sVs[idx] = *(const float4*)&V[(size_t)(h * SS + j0) * DDIM + idx];
        }

        // Prefetch streaming bias inputs for this block's 4x4 fragment
        float4 d4[4], e4[4]; int4 mk4[4];
#pragma unroll
        for (int r = 0; r < 4; r++) {
            size_t off = ((size_t)(h * SS) + i0 + 4 * ty + r) * SS + j0 + 4 * tx;
            d4[r]  = *(const float4*)&dist[off];
            e4[r]  = *(const float4*)&energy[off];
            mk4[r] = *(const int4*)&mask[off];
        }
        __syncthreads();

        // ---- S = Q K^T (4x4 micro-tile, d-major smem, LDS.128 operands) ----
        float sv[4][4] = {};
#pragma unroll 8
        for (int d = 0; d < DDIM; d++) {
            float4 q = *(const float4*)&sQt[d * 64 + 4 * ty];
            float4 k = *(const float4*)&sKt[d * 64 + 4 * tx];
            float qa[4] = {q.x, q.y, q.z, q.w};
            float ka[4] = {k.x, k.y, k.z, k.w};
#pragma unroll
            for (int r = 0; r < 4; r++)
#pragma unroll
                for (int c = 0; c < 4; c++)
                    sv[r][c] = fmaf(qa[r], ka[c], sv[r][c]);
        }

        // ---- scale + LUT biases + mask ----
#pragma unroll
        for (int r = 0; r < 4; r++) {
            float dv[4] = {d4[r].x, d4[r].y, d4[r].z, d4[r].w};
            float ev[4] = {e4[r].x, e4[r].y, e4[r].z, e4[r].w};
            int   mv[4] = {mk4[r].x, mk4[r].y, mk4[r].z, mk4[r].w};
#pragma unroll
            for (int c = 0; c < 4; c++) {
                float tD = fminf(fmaxf((dv[c] - D_LO) * DINV, 0.0f), (float)(NLUT - 1) - 1e-3f);
                float tE = fminf(fmaxf((ev[c] - E_LO) * EINV, 0.0f), (float)(NLUT - 1) - 1e-3f);
                int   iD = (int)tD;     int iE = (int)tE;
                float fD = tD - (float)iD;
                float fE = tE - (float)iE;
                float2 eD = sLD[iD];
                float2 eE = sLE[iE];
                float val = sv[r][c] * SCALE + fmaf(fD, eD.y, eD.x) + fmaf(fE, eE.y, eE.x);
                sv[r][c] = (mv[c] != 0) ? val : -1e9f;
            }
        }

        // ---- online softmax (row reductions across the 16 tx lanes) ----
#pragma unroll
        for (int r = 0; r < 4; r++) {
            float mt = fmaxf(fmaxf(sv[r][0], sv[r][1]), fmaxf(sv[r][2], sv[r][3]));
#pragma unroll
            for (int o = 1; o < 16; o <<= 1)
                mt = fmaxf(mt, __shfl_xor_sync(0xffffffffu, mt, o));
            float mnew  = fmaxf(mrow[r], mt);
            float alpha = __expf(mrow[r] - mnew);
            mrow[r] = mnew;
            float rs = 0.0f;
#pragma unroll
            for (int c = 0; c < 4; c++) { sv[r][c] = __expf(sv[r][c] - mnew); rs += sv[r][c]; }
#pragma unroll
            for (int o = 1; o < 16; o <<= 1)
                rs += __shfl_xor_sync(0xffffffffu, rs, o);
            lrow[r] = lrow[r] * alpha + rs;
#pragma unroll
            for (int c = 0; c < 4; c++) acc[r][c] *= alpha;
        }

        // ---- P -> smem (j-major, XOR swizzle on 16B chunks: conflict-free) ----
#pragma unroll
        for (int c = 0; c < 4; c++) {
            int j = 4 * tx + c;
            float4 pv = make_float4(sv[0][c], sv[1][c], sv[2][c], sv[3][c]);
            *(float4*)&sP[j * 64 + ((ty ^ (j & 15)) << 2)] = pv;
        }
        __syncthreads();

        // ---- O += P V ----
#pragma unroll 8
        for (int j = 0; j < BN; j++) {
            float4 p = *(const float4*)&sP[j * 64 + ((ty ^ (j & 15)) << 2)];
            float4 v = *(const float4*)&sVs[j * 64 + 4 * tx];
            float pa[4] = {p.x, p.y, p.z, p.w};
            float va[4] = {v.x, v.y, v.z, v.w};
#pragma unroll
            for (int r = 0; r < 4; r++)
#pragma unroll
                for (int c = 0; c < 4; c++)
                    acc[r][c] = fmaf(pa[r], va[c], acc[r][c]);
        }
    }

    // ---- normalize + write output ----
#pragma unroll
    for (int r = 0; r < 4; r++) {
        float inv = 1.0f / lrow[r];
        float4 o = make_float4(acc[r][0] * inv, acc[r][1] * inv,
                               acc[r][2] * inv, acc[r][3] * inv);
        *(float4*)&out[((size_t)(h * SS) + i0 + 4 * ty + r) * DDIM + 4 * tx] = o;
    }
}

// ---------------------------------------------------------------------------
extern "C" void kernel_launch(void* const* d_in, const int* in_sizes, int n_in,
                              void* d_out, int out_size)
{
    const float* Q      = (const float*)d_in[0];
    const float* K      = (const float*)d_in[1];
    const float* V      = (const float*)d_in[2];
    const float* dist   = (const float*)d_in[3];
    const float* energy = (const float*)d_in[4];
    const int*   mask   = (const int*)  d_in[5];
    const float* mu_D   = (const float*)d_in[6];
    const float* sg_D   = (const float*)d_in[7];
    const float* b_D    = (const float*)d_in[8];
    const float* mu_E   = (const float*)d_in[9];
    const float* sg_E   = (const float*)d_in[10];
    const float* b_E    = (const float*)d_in[11];
    const float* W1     = (const float*)d_in[12];
    const float* b1     = (const float*)d_in[13];
    const float* W2     = (const float*)d_in[14];
    const float* b2     = (const float*)d_in[15];
    float* out = (float*)d_out;

    // 1) transpose Q,K into d-major scratch
    transpose_qk_kernel<<<dim3(SS / 32, DDIM / 32, HH * 2), dim3(32, 8)>>>(Q, K);

    // 2) build the two bias LUTs
    build_lut_kernel<<<(2 * NLUT + 255) / 256, 256>>>(
        mu_D, sg_D, b_D, mu_E, sg_E, b_E, W1, b1, W2, b2);

    // 3) fused attention
    const int SMEM_BYTES = (16384 * 4) + (2 * NLUT * 8);   // 64KB tiles + 64KB LUTs
    cudaFuncSetAttribute(attn_kernel,
                         cudaFuncAttributeMaxDynamicSharedMemorySize, SMEM_BYTES);
    attn_kernel<<<dim3(SS / BM, HH), 256, SMEM_BYTES>>>(V, dist, energy, mask, out);
}

// round 2
// speedup vs baseline: 1.0101x; 1.0101x over previous
#include <cuda_runtime.h>
#include <math.h>

#define HH   8
#define SS   1024
#define DDIM 64
#define KG   10
#define NLUT 4096
#define BM   64
#define BN   64

#define D_LO (-0.05f)
#define D_HI (10.05f)
#define E_LO (-0.05f)
#define E_HI (5.05f)

// Scratch (no runtime allocation allowed): transposed Q/K and the bias LUTs.
__device__ float  g_Qt[HH * DDIM * SS];   // [h][d][s]
__device__ float  g_Kt[HH * DDIM * SS];   // [h][d][s]
__device__ float2 g_lutD[NLUT];           // {value, delta-to-next}
__device__ float2 g_lutE[NLUT];

// ---------------------------------------------------------------------------
// Exact bias function (RBF features -> Linear -> exact GELU -> Linear).
// Evaluated only NLUT*2*2 times total, so full-precision expf/erff.
// ---------------------------------------------------------------------------
__device__ __forceinline__ float bias_eval(
    float x,
    const float* __restrict__ mu, const float* __restrict__ sg,
    const float* __restrict__ bb,
    const float* __restrict__ W1, const float* __restrict__ b1,
    const float* __restrict__ W2, const float* __restrict__ b2)
{
    float psi[KG];
#pragma unroll
    for (int k = 0; k < KG; k++) {
        float s = sg[k];
        float z = (x + bb[k] - mu[k]) / s;
        psi[k] = expf(-0.5f * z * z) * (0.3989422804014327f / s);
    }
    float o = b2[0];
#pragma unroll
    for (int l = 0; l < KG; l++) {
        float a = b1[l];
#pragma unroll
        for (int k = 0; k < KG; k++) a = fmaf(psi[k], W1[l * KG + k], a);
        float g = 0.5f * a * (1.0f + erff(a * 0.7071067811865476f));
        o = fmaf(g, W2[l], o);
    }
    return o;
}

__global__ void build_lut_kernel(
    const float* __restrict__ muD, const float* __restrict__ sgD, const float* __restrict__ bD,
    const float* __restrict__ muE, const float* __restrict__ sgE, const float* __restrict__ bE,
    const float* __restrict__ W1,  const float* __restrict__ b1,
    const float* __restrict__ W2,  const float* __restrict__ b2)
{
    int i = blockIdx.x * blockDim.x + threadIdx.x;
    if (i >= 2 * NLUT) return;
    int which = i >> 12;        // 0 = distance table, 1 = energy table
    int e     = i & (NLUT - 1);

    float lo = which ? E_LO : D_LO;
    float hi = which ? E_HI : D_HI;
    float dx = (hi - lo) / (float)(NLUT - 1);
    float x0 = lo + (float)e * dx;

    const float* mu = which ? muE : muD;
    const float* sg = which ? sgE : sgD;
    const float* bb = which ? bE  : bD;

    float f0 = bias_eval(x0,      mu, sg, bb, W1, b1, W2, b2);
    float f1 = bias_eval(x0 + dx, mu, sg, bb, W1, b1, W2, b2);
    float2 entry = make_float2(f0, f1 - f0);
    if (which) g_lutE[e] = entry; else g_lutD[e] = entry;
}

// ---------------------------------------------------------------------------
// Pre-transpose Q and K: [h][s][d] -> [h][d][s] so the attention kernel can do
// conflict-free d-major smem tiles with LDS.128.
// ---------------------------------------------------------------------------
__global__ void transpose_qk_kernel(const float* __restrict__ Q,
                                    const float* __restrict__ K)
{
    __shared__ float tile[32][33];
    int h = blockIdx.z >> 1;
    const float* src = (blockIdx.z & 1) ? K : Q;
    float*       dst = (blockIdx.z & 1) ? g_Kt : g_Qt;
    int s0 = blockIdx.x * 32;
    int d0 = blockIdx.y * 32;
    int tx = threadIdx.x, ty = threadIdx.y;
#pragma unroll
    for (int k = 0; k < 32; k += 8)
        tile[ty + k][tx] = src[((h * SS) + (s0 + ty + k)) * DDIM + d0 + tx];
    __syncthreads();
#pragma unroll
    for (int k = 0; k < 32; k += 8)
        dst[((h * DDIM) + (d0 + ty + k)) * SS + s0 + tx] = tile[tx][ty + k];
}

// ---------------------------------------------------------------------------
// Fused flash-attention with LUT biases.
// Grid: (S/BM, H). Block: 256 threads = 16x16; thread (ty,tx) owns a 4x4
// micro-tile: rows 4ty..4ty+3, cols/dims 4tx..4tx+3.
// Dynamic smem (128KB): Qt[64][64] | Kt[64][64] | V[64][64] | Pswz[64][64]
//                       | lutD float2[4096] | lutE float2[4096]
// ---------------------------------------------------------------------------
__global__ __launch_bounds__(256, 1) void attn_kernel(
    const float* __restrict__ V,
    const float* __restrict__ dist,
    const float* __restrict__ energy,
    const int*   __restrict__ mask,
    float*       __restrict__ out)
{
    extern __shared__ float sm[];
    float*  sQt = sm;                 // [d][row]   4096 floats
    float*  sKt = sm + 4096;          // [d][col]   4096 floats
    float*  sVs = sm + 8192;          // [j][dim]   4096 floats
    float*  sP  = sm + 12288;         // [j][row]   4096 floats, XOR-swizzled
    float2* sLD = (float2*)(sm + 16384);
    float2* sLE = (float2*)(sm + 24576);

    const int tid = threadIdx.x;
    const int tx  = tid & 15;
    const int ty  = tid >> 4;
    const int h   = blockIdx.y;
    const int i0  = blockIdx.x * BM;

    const float SCALE = 0.08838834764831845f;   // 1/sqrt(2*D)
    const float DINV  = (float)(NLUT - 1) / (D_HI - D_LO);
    const float EINV  = (float)(NLUT - 1) / (E_HI - E_LO);

    // LUTs -> shared (once per block)
    for (int i = tid; i < NLUT; i += 256) { sLD[i] = g_lutD[i]; sLE[i] = g_lutE[i]; }

    // Q tile (d-major), coalesced float4 copy
#pragma unroll
    for (int it = 0; it < 4; it++) {
        int idx = tid * 4 + it * 1024;
        int d = idx >> 6, r = idx & 63;
        *(float4*)&sQt[idx] = *(const float4*)&g_Qt[(h * DDIM + d) * SS + i0 + r];
    }

    float acc[4][4] = {};
    float mrow[4]   = {-1e30f, -1e30f, -1e30f, -1e30f};
    float lrow[4]   = {};

    for (int jt = 0; jt < SS / BN; jt++) {
        const int j0 = jt * BN;
        __syncthreads();   // previous iteration done reading sKt/sVs/sP

        // K tile (d-major) + V tile (natural), coalesced float4 copies
#pragma unroll
        for (int it = 0; it < 4; it++) {
            int idx = tid * 4 + it * 1024;
            int d = idx >> 6, r = idx & 63;
            *(float4*)&sKt[idx] = *(const float4*)&g_Kt[(h * DDIM + d) * SS + j0 + r];
            *(float4*)&sVs[idx] = *(const float4*)&V[(size_t)(h * SS + j0) * DDIM + idx];
        }

        // Prefetch streaming bias inputs for this block's 4x4 fragment
        float4 d4[4], e4[4]; int4 mk4[4];
#pragma unroll
        for (int r = 0; r < 4; r++) {
            size_t off = ((size_t)(h * SS) + i0 + 4 * ty + r) * SS + j0 + 4 * tx;
            d4[r]  = *(const float4*)&dist[off];
            e4[r]  = *(const float4*)&energy[off];
            mk4[r] = *(const int4*)&mask[off];
        }
        __syncthreads();

        // ---- S = Q K^T (4x4 micro-tile, d-major smem, LDS.128 operands) ----
        float sv[4][4] = {};
#pragma unroll 8
        for (int d = 0; d < DDIM; d++) {
            float4 q = *(const float4*)&sQt[d * 64 + 4 * ty];
            float4 k = *(const float4*)&sKt[d * 64 + 4 * tx];
            float qa[4] = {q.x, q.y, q.z, q.w};
            float ka[4] = {k.x, k.y, k.z, k.w};
#pragma unroll
            for (int r = 0; r < 4; r++)
#pragma unroll
                for (int c = 0; c < 4; c++)
                    sv[r][c] = fmaf(qa[r], ka[c], sv[r][c]);
        }

        // ---- scale + LUT biases + mask ----
#pragma unroll
        for (int r = 0; r < 4; r++) {
            float dv[4] = {d4[r].x, d4[r].y, d4[r].z, d4[r].w};
            float ev[4] = {e4[r].x, e4[r].y, e4[r].z, e4[r].w};
            int   mv[4] = {mk4[r].x, mk4[r].y, mk4[r].z, mk4[r].w};
#pragma unroll
            for (int c = 0; c < 4; c++) {
                float tD = fminf(fmaxf((dv[c] - D_LO) * DINV, 0.0f), (float)(NLUT - 1) - 1e-3f);
                float tE = fminf(fmaxf((ev[c] - E_LO) * EINV, 0.0f), (float)(NLUT - 1) - 1e-3f);
                int   iD = (int)tD;     int iE = (int)tE;
                float fD = tD - (float)iD;
                float fE = tE - (float)iE;
                float2 eD = sLD[iD];
                float2 eE = sLE[iE];
                float val = sv[r][c] * SCALE + fmaf(fD, eD.y, eD.x) + fmaf(fE, eE.y, eE.x);
                sv[r][c] = (mv[c] != 0) ? val : -1e9f;
            }
        }

        // ---- online softmax (row reductions across the 16 tx lanes) ----
#pragma unroll
        for (int r = 0; r < 4; r++) {
            float mt = fmaxf(fmaxf(sv[r][0], sv[r][1]), fmaxf(sv[r][2], sv[r][3]));
#pragma unroll
            for (int o = 1; o < 16; o <<= 1)
                mt = fmaxf(mt, __shfl_xor_sync(0xffffffffu, mt, o));
            float mnew  = fmaxf(mrow[r], mt);
            float alpha = __expf(mrow[r] - mnew);
            mrow[r] = mnew;
            float rs = 0.0f;
#pragma unroll
            for (int c = 0; c < 4; c++) { sv[r][c] = __expf(sv[r][c] - mnew); rs += sv[r][c]; }
#pragma unroll
            for (int o = 1; o < 16; o <<= 1)
                rs += __shfl_xor_sync(0xffffffffu, rs, o);
            lrow[r] = lrow[r] * alpha + rs;
#pragma unroll
            for (int c = 0; c < 4; c++) acc[r][c] *= alpha;
        }

        // ---- P -> smem (j-major, XOR swizzle on 16B chunks: conflict-free) ----
#pragma unroll
        for (int c = 0; c < 4; c++) {
            int j = 4 * tx + c;
            float4 pv = make_float4(sv[0][c], sv[1][c], sv[2][c], sv[3][c]);
            *(float4*)&sP[j * 64 + ((ty ^ (j & 15)) << 2)] = pv;
        }
        __syncthreads();

        // ---- O += P V ----
#pragma unroll 8
        for (int j = 0; j < BN; j++) {
            float4 p = *(const float4*)&sP[j * 64 + ((ty ^ (j & 15)) << 2)];
            float4 v = *(const float4*)&sVs[j * 64 + 4 * tx];
            float pa[4] = {p.x, p.y, p.z, p.w};
            float va[4] = {v.x, v.y, v.z, v.w};
#pragma unroll
            for (int r = 0; r < 4; r++)
#pragma unroll
                for (int c = 0; c < 4; c++)
                    acc[r][c] = fmaf(pa[r], va[c], acc[r][c]);
        }
    }

    // ---- normalize + write output ----
#pragma unroll
    for (int r = 0; r < 4; r++) {
        float inv = 1.0f / lrow[r];
        float4 o = make_float4(acc[r][0] * inv, acc[r][1] * inv,
                               acc[r][2] * inv, acc[r][3] * inv);
        *(float4*)&out[((size_t)(h * SS) + i0 + 4 * ty + r) * DDIM + 4 * tx] = o;
    }
}

// ---------------------------------------------------------------------------
extern "C" void kernel_launch(void* const* d_in, const int* in_sizes, int n_in,
                              void* d_out, int out_size)
{
    const float* Q      = (const float*)d_in[0];
    const float* K      = (const float*)d_in[1];
    const float* V      = (const float*)d_in[2];
    const float* dist   = (const float*)d_in[3];
    const float* energy = (const float*)d_in[4];
    const int*   mask   = (const int*)  d_in[5];
    const float* mu_D   = (const float*)d_in[6];
    const float* sg_D   = (const float*)d_in[7];
    const float* b_D    = (const float*)d_in[8];
    const float* mu_E   = (const float*)d_in[9];
    const float* sg_E   = (const float*)d_in[10];
    const float* b_E    = (const float*)d_in[11];
    const float* W1     = (const float*)d_in[12];
    const float* b1     = (const float*)d_in[13];
    const float* W2     = (const float*)d_in[14];
    const float* b2     = (const float*)d_in[15];
    float* out = (float*)d_out;

    // 1) transpose Q,K into d-major scratch
    transpose_qk_kernel<<<dim3(SS / 32, DDIM / 32, HH * 2), dim3(32, 8)>>>(Q, K);

    // 2) build the two bias LUTs
    build_lut_kernel<<<(2 * NLUT + 255) / 256, 256>>>(
        mu_D, sg_D, b_D, mu_E, sg_E, b_E, W1, b1, W2, b2);

    // 3) fused attention
    const int SMEM_BYTES = (16384 * 4) + (2 * NLUT * 8);   // 64KB tiles + 64KB LUTs
    cudaFuncSetAttribute(attn_kernel,
                         cudaFuncAttributeMaxDynamicSharedMemorySize, SMEM_BYTES);
    attn_kernel<<<dim3(SS / BM, HH), 256, SMEM_BYTES>>>(V, dist, energy, mask, out);
}